// round 11
// baseline (speedup 1.0000x reference)
#include <cuda_runtime.h>
#include <cuda_fp16.h>
#include <cstdint>
#include <cstddef>

#define T_STEPS  511
#define BATCH    1024
#define NBLK     128
#define NTHREADS 128
#define XELEM    66977792u     /* 511*1024*128 */
#define XWORDS4  16744448u     /* XELEM/4 */

// SMEM layout (bytes, all offsets 128B-aligned)
#define OFF_BH   0u            /* B hi: 64 rows x 784B  = 50176 */
#define OFF_BL   50176u        /* B lo                          */
#define OFF_BIAS 100352u       /* 64 floats                     */
#define OFF_AH   100608u       /* A hi chunk: 128 x 400B = 51200*/
#define OFF_AL   151808u       /* A lo chunk                    */
#define SMEM_DYN 203008u
#define OFF_HSH  OFF_AH        /* h staging reuses A region     */
#define OFF_HSL  (OFF_AH + 4096u)

// ---------------------------------------------------------------- helpers
__device__ __forceinline__ uint32_t smem_u32(const void* p) {
    uint32_t a;
    asm("{ .reg .u64 t; cvta.to.shared.u64 t, %1; cvt.u32.u64 %0, t; }"
        : "=r"(a) : "l"(p));
    return a;
}
__device__ __forceinline__ void ldsm4(uint32_t* r, uint32_t addr) {
    asm volatile("ldmatrix.sync.aligned.m8n8.x4.shared.b16 {%0,%1,%2,%3}, [%4];"
        : "=r"(r[0]), "=r"(r[1]), "=r"(r[2]), "=r"(r[3]) : "r"(addr));
}
__device__ __forceinline__ void mma16816(float* c, const uint32_t* a,
                                         const uint32_t* b) {
    asm volatile(
        "mma.sync.aligned.m16n8k16.row.col.f32.f16.f16.f32 "
        "{%0,%1,%2,%3}, {%4,%5,%6,%7}, {%8,%9}, {%0,%1,%2,%3};"
        : "+f"(c[0]), "+f"(c[1]), "+f"(c[2]), "+f"(c[3])
        : "r"(a[0]), "r"(a[1]), "r"(a[2]), "r"(a[3]), "r"(b[0]), "r"(b[1]));
}
__device__ __forceinline__ void cpa16(uint32_t dst, const void* src) {
    asm volatile("cp.async.cg.shared.global [%0], [%1], 16;"
        :: "r"(dst), "l"(src) : "memory");
}
#define CP_COMMIT() asm volatile("cp.async.commit_group;" ::: "memory")
#define CP_WAIT0()  asm volatile("cp.async.wait_group 0;"  ::: "memory")

__device__ __forceinline__ float sigf(float x) {
    return __fdividef(1.f, 1.f + __expf(-x));
}
__device__ __forceinline__ float tanhf_fast(float x) {
    return 1.f - __fdividef(2.f, __expf(2.f * x) + 1.f);
}

// ---------------------------------------------------------------- scratch
__device__ __align__(16) __half g_xhi[XELEM];
__device__ __align__(16) __half g_xlo[XELEM];
__device__ __align__(16) __half g_hhi[2][BATCH * 256];
__device__ __align__(16) __half g_hlo[2][BATCH * 256];
__device__ unsigned g_cnt[8];
__device__ unsigned g_gen[8];

// ---------------------------------------------------------------- prepass
__global__ void lstm_split_x(const float4* __restrict__ x) {
    uint32_t i = blockIdx.x * blockDim.x + threadIdx.x;
    if (i >= XWORDS4) return;
    float4 v = x[i];
    union U { __half h[4]; uint2 u; } ph, pl;
    ph.h[0] = __float2half_rn(v.x); ph.h[1] = __float2half_rn(v.y);
    ph.h[2] = __float2half_rn(v.z); ph.h[3] = __float2half_rn(v.w);
    pl.h[0] = __float2half_rn(v.x - __half2float(ph.h[0]));
    pl.h[1] = __float2half_rn(v.y - __half2float(ph.h[1]));
    pl.h[2] = __float2half_rn(v.z - __half2float(ph.h[2]));
    pl.h[3] = __float2half_rn(v.w - __half2float(ph.h[3]));
    ((uint2*)g_xhi)[i] = ph.u;
    ((uint2*)g_xlo)[i] = pl.u;
}

// ---------------------------------------------------------------- barrier
// Only CTAs sharing a batch-block (mb) depend on each other: 16-CTA groups.
__device__ __forceinline__ void group_barrier(int mb) {
    __syncthreads();
    if (threadIdx.x == 0) {
        __threadfence();
        unsigned g0 = ((volatile unsigned*)g_gen)[mb];
        if (atomicAdd(&g_cnt[mb], 1u) == 15u) {
            ((volatile unsigned*)g_cnt)[mb] = 0u;
            __threadfence();
            atomicAdd(&g_gen[mb], 1u);
        } else {
            while (((volatile unsigned*)g_gen)[mb] == g0) { __nanosleep(32); }
        }
        __threadfence();
    }
    __syncthreads();
}

// ---------------------------------------------------------------- main
__global__ void __launch_bounds__(NTHREADS, 1) lstm_persistent(
    const float* __restrict__ W_ih, const float* __restrict__ W_hh,
    const float* __restrict__ b_ih, const float* __restrict__ b_hh,
    const float* __restrict__ hx0, const float* __restrict__ cx0,
    float* __restrict__ out)
{
    extern __shared__ char sm[];
    const uint32_t sb = smem_u32(sm);

    const int tid  = threadIdx.x;
    const int lane = tid & 31;
    const int w    = tid >> 5;
    const int wm   = w >> 1;          // 0..1: rows [wm*64, +64)
    const int wn   = w & 1;           // 0..1: cols [wn*32, +32)
    const int mb   = blockIdx.x >> 4; // batch block (128 rows)
    const int nb   = blockIdx.x & 15; // 16 h-channels

    // ---- build B (hi/lo fp16, [n][k] K-contig, row stride 784B) + bias ----
    // col n: gate g=(n>>3)&3, ch=(n&7)+((n>>5)<<3)  (each 32-col half has all
    // 4 gates for 8 channels -> every thread owns complete i,f,g,o quads)
    for (int idx = tid; idx < 64 * 384; idx += NTHREADS) {
        int n = idx / 384, k = idx - n * 384;
        int g = (n >> 3) & 3, ch = (n & 7) + ((n >> 5) << 3);
        int wr = g * 256 + nb * 16 + ch;
        float v = (k < 128) ? W_ih[wr * 128 + k] : W_hh[wr * 256 + (k - 128)];
        __half hi = __float2half_rn(v);
        __half lo = __float2half_rn(v - __half2float(hi));
        *(__half*)(sm + OFF_BH + n * 784 + k * 2) = hi;
        *(__half*)(sm + OFF_BL + n * 784 + k * 2) = lo;
    }
    if (tid < 64) {
        int g = (tid >> 3) & 3, ch = (tid & 7) + ((tid >> 5) << 3);
        int wr = g * 256 + nb * 16 + ch;
        ((float*)(sm + OFF_BIAS))[tid] = b_ih[wr] + b_hh[wr];
    }

    // ---- init c registers + h0 ping buffer 0 ----
    const int lc2 = 2 * (lane & 3);
    float c_reg[16], h_f[16];
#pragma unroll
    for (int mi = 0; mi < 4; mi++)
#pragma unroll
        for (int rr = 0; rr < 2; rr++)
#pragma unroll
            for (int cc = 0; cc < 2; cc++) {
                int ch = 8 * wn + lc2 + cc;
                c_reg[mi * 4 + rr * 2 + cc] = cx0[nb * 16 + ch];
                h_f[mi * 4 + rr * 2 + cc] = 0.f;
            }
    {
        int r = tid;                    // this CTA covers rows mb*128+r
        size_t o = ((size_t)(mb * 128 + r)) * 256 + nb * 16;
#pragma unroll
        for (int ch = 0; ch < 16; ch++) {
            float v = hx0[nb * 16 + ch];
            __half hi = __float2half_rn(v);
            __half lo = __float2half_rn(v - __half2float(hi));
            g_hhi[0][o + ch] = hi;
            g_hlo[0][o + ch] = lo;
        }
    }
    group_barrier(mb);

    // ---- recurrence ----
    for (int t = 0; t < T_STEPS; t++) {
        const int pr = t & 1, pw = pr ^ 1;
        const __half* xh = g_xhi + ((size_t)t * BATCH + mb * 128) * 128;
        const __half* xl = g_xlo + ((size_t)t * BATCH + mb * 128) * 128;
        const __half* hh = g_hhi[pr] + (size_t)(mb * 128) * 256;
        const __half* hl = g_hlo[pr] + (size_t)(mb * 128) * 256;

        float Cacc[4][4][4];
#pragma unroll
        for (int mi = 0; mi < 4; mi++)
#pragma unroll
            for (int ni = 0; ni < 4; ni++)
#pragma unroll
                for (int e = 0; e < 4; e++) Cacc[mi][ni][e] = 0.f;

        for (int ck = 0; ck < 2; ck++) {          // K chunks [0,192),[192,384)
            // fill A chunk (hi/lo), 16B cp.async, 24 iters x 2 per thread
            for (int idx = tid; idx < 128 * 24; idx += NTHREADS) {
                int row = idx / 24, kc = idx - row * 24;
                int gk = ck * 192 + kc * 8;       // global k (halves)
                const __half *sh, *sl;
                if (gk < 128) { sh = xh + row * 128 + gk;
                                sl = xl + row * 128 + gk; }
                else          { sh = hh + row * 256 + (gk - 128);
                                sl = hl + row * 256 + (gk - 128); }
                uint32_t d = sb + OFF_AH + row * 400 + kc * 16;
                cpa16(d, sh);
                cpa16(d + (OFF_AL - OFF_AH), sl);
            }
            CP_COMMIT();
            CP_WAIT0();
            __syncthreads();

            const int kb2 = ck * 384;             // B byte k-offset base
#pragma unroll
            for (int ks = 0; ks < 12; ks++) {
                uint32_t ah[4][4], al[4][4], bh2[2][4], bl2[2][4];
#pragma unroll
                for (int mi = 0; mi < 4; mi++) {
                    uint32_t row = wm * 64 + mi * 16 + (lane & 15);
                    uint32_t a = sb + OFF_AH + row * 400 + ks * 32
                               + ((lane >> 4) << 4);
                    ldsm4(ah[mi], a);
                    ldsm4(al[mi], a + (OFF_AL - OFF_AH));
                }
#pragma unroll
                for (int gn = 0; gn < 2; gn++) {
                    uint32_t n = wn * 32 + gn * 16 + (lane & 7)
                               + ((lane >> 4) << 3);
                    uint32_t ko = ((lane >> 3) & 1) * 16;   // bytes (8 halves)
                    uint32_t a = sb + OFF_BH + n * 784 + kb2 + ks * 32 + ko;
                    ldsm4(bh2[gn], a);
                    ldsm4(bl2[gn], a + (OFF_BL - OFF_BH));
                }
#pragma unroll
                for (int mi = 0; mi < 4; mi++)
#pragma unroll
                    for (int ni = 0; ni < 4; ni++) {
                        const uint32_t* bH = &bh2[ni >> 1][(ni & 1) * 2];
                        const uint32_t* bL = &bl2[ni >> 1][(ni & 1) * 2];
                        mma16816(Cacc[mi][ni], ah[mi], bH);  // Ahi*Bhi
                        mma16816(Cacc[mi][ni], al[mi], bH);  // Alo*Bhi
                        mma16816(Cacc[mi][ni], ah[mi], bL);  // Ahi*Blo
                    }
            }
            __syncthreads();   // all warps done with this A chunk
        }

        // ---- in-register epilogue: gates -> (h,c); h hi/lo to smem ----
        const float* bias = (const float*)(sm + OFF_BIAS);
#pragma unroll
        for (int mi = 0; mi < 4; mi++)
#pragma unroll
            for (int rr = 0; rr < 2; rr++)
#pragma unroll
                for (int cc = 0; cc < 2; cc++) {
                    int ci = rr * 2 + cc;
                    int idx = mi * 4 + ci;
                    int ch = 8 * wn + lc2 + cc;
                    float gi = Cacc[mi][0][ci] + bias[wn * 32 + 0  + lc2 + cc];
                    float gf = Cacc[mi][1][ci] + bias[wn * 32 + 8  + lc2 + cc];
                    float gg = Cacc[mi][2][ci] + bias[wn * 32 + 16 + lc2 + cc];
                    float go = Cacc[mi][3][ci] + bias[wn * 32 + 24 + lc2 + cc];
                    float i_ = sigf(gi), f_ = sigf(gf);
                    float g_ = tanhf_fast(gg), o_ = sigf(go);
                    float cn = f_ * c_reg[idx] + i_ * g_;
                    c_reg[idx] = cn;
                    float hN = o_ * tanhf_fast(cn);
                    h_f[idx] = hN;
                    int r = wm * 64 + mi * 16 + (lane >> 2) + rr * 8;
                    __half hi = __float2half_rn(hN);
                    __half lo = __float2half_rn(hN - __half2float(hi));
                    *(__half*)(sm + OFF_HSH + r * 32 + ch * 2) = hi;
                    *(__half*)(sm + OFF_HSL + r * 32 + ch * 2) = lo;
                }
        __syncthreads();

        // coalesced h -> gmem ping buffer
        {
            int r = tid;
            const uint4* s0 = (const uint4*)(sm + OFF_HSH + r * 32);
            const uint4* s1 = (const uint4*)(sm + OFF_HSL + r * 32);
            size_t o = ((size_t)(mb * 128 + r)) * 256 + nb * 16;
            *(uint4*)(g_hhi[pw] + o)     = s0[0];
            *(uint4*)(g_hhi[pw] + o + 8) = s0[1];
            *(uint4*)(g_hlo[pw] + o)     = s1[0];
            *(uint4*)(g_hlo[pw] + o + 8) = s1[1];
        }
        group_barrier(mb);
    }

    // ---- output: h (1024x256) then c (1024x256), fp32 ----
#pragma unroll
    for (int mi = 0; mi < 4; mi++)
#pragma unroll
        for (int rr = 0; rr < 2; rr++)
#pragma unroll
            for (int cc = 0; cc < 2; cc++) {
                int idx = mi * 4 + rr * 2 + cc;
                int r = wm * 64 + mi * 16 + (lane >> 2) + rr * 8;
                int ch = 8 * wn + lc2 + cc;
                size_t o = ((size_t)(mb * 128 + r)) * 256 + nb * 16 + ch;
                out[o] = h_f[idx];
                out[(size_t)BATCH * 256 + o] = c_reg[idx];
            }
}

// ---------------------------------------------------------------- launch
extern "C" void kernel_launch(void* const* d_in, const int* in_sizes, int n_in,
                              void* d_out, int out_size) {
    (void)in_sizes; (void)n_in; (void)out_size;
    const float* x    = (const float*)d_in[0];
    const float* W_ih = (const float*)d_in[1];
    const float* W_hh = (const float*)d_in[2];
    const float* b_ih = (const float*)d_in[3];
    const float* b_hh = (const float*)d_in[4];
    const float* hx0  = (const float*)d_in[5];
    const float* cx0  = (const float*)d_in[6];
    float* out = (float*)d_out;

    cudaFuncSetAttribute(lstm_persistent,
                         cudaFuncAttributeMaxDynamicSharedMemorySize, SMEM_DYN);

    lstm_split_x<<<(XWORDS4 + 255) / 256, 256>>>((const float4*)x);
    lstm_persistent<<<NBLK, NTHREADS, SMEM_DYN>>>(W_ih, W_hh, b_ih, b_hh,
                                                  hx0, cx0, out);
}

// round 12
// speedup vs baseline: 1.0163x; 1.0163x over previous
#include <cuda_runtime.h>
#include <cuda_fp16.h>
#include <cstdint>
#include <cstddef>

#define T_STEPS  511
#define BATCH    1024
#define NBLK     128
#define NTHREADS 256
#define XELEM    66977792u     /* 511*1024*128 */
#define XWORDS4  16744448u     /* XELEM/4 */

// SMEM layout (bytes, all offsets 128B-aligned)
#define OFF_BH   0u            /* B hi: 64 rows x 784B  = 50176 */
#define OFF_BL   50176u        /* B lo                          */
#define OFF_BIAS 100352u       /* 64 floats                     */
#define OFF_AH   100608u       /* A hi chunk: 128 x 400B = 51200*/
#define OFF_AL   151808u       /* A lo chunk                    */
#define SMEM_DYN 203008u
#define OFF_HSH  OFF_AH        /* h staging reuses A region     */
#define OFF_HSL  (OFF_AH + 4096u)

// ---------------------------------------------------------------- helpers
__device__ __forceinline__ uint32_t smem_u32(const void* p) {
    uint32_t a;
    asm("{ .reg .u64 t; cvta.to.shared.u64 t, %1; cvt.u32.u64 %0, t; }"
        : "=r"(a) : "l"(p));
    return a;
}
__device__ __forceinline__ void ldsm4(uint32_t* r, uint32_t addr) {
    asm volatile("ldmatrix.sync.aligned.m8n8.x4.shared.b16 {%0,%1,%2,%3}, [%4];"
        : "=r"(r[0]), "=r"(r[1]), "=r"(r[2]), "=r"(r[3]) : "r"(addr));
}
__device__ __forceinline__ void mma16816(float* c, const uint32_t* a,
                                         const uint32_t* b) {
    asm volatile(
        "mma.sync.aligned.m16n8k16.row.col.f32.f16.f16.f32 "
        "{%0,%1,%2,%3}, {%4,%5,%6,%7}, {%8,%9}, {%0,%1,%2,%3};"
        : "+f"(c[0]), "+f"(c[1]), "+f"(c[2]), "+f"(c[3])
        : "r"(a[0]), "r"(a[1]), "r"(a[2]), "r"(a[3]), "r"(b[0]), "r"(b[1]));
}
__device__ __forceinline__ void cpa16(uint32_t dst, const void* src) {
    asm volatile("cp.async.cg.shared.global [%0], [%1], 16;"
        :: "r"(dst), "l"(src) : "memory");
}
#define CP_COMMIT() asm volatile("cp.async.commit_group;" ::: "memory")
#define CP_WAIT0()  asm volatile("cp.async.wait_group 0;"  ::: "memory")

__device__ __forceinline__ float sigf(float x) {
    return __fdividef(1.f, 1.f + __expf(-x));
}
__device__ __forceinline__ float tanhf_fast(float x) {
    return 1.f - __fdividef(2.f, __expf(2.f * x) + 1.f);
}

// ---------------------------------------------------------------- scratch
__device__ __align__(16) __half g_xhi[XELEM];
__device__ __align__(16) __half g_xlo[XELEM];
__device__ __align__(16) __half g_hhi[2][BATCH * 256];
__device__ __align__(16) __half g_hlo[2][BATCH * 256];
__device__ unsigned g_cnt[8];
__device__ unsigned g_gen[8];

// ---------------------------------------------------------------- prepass
__global__ void lstm_split_x(const float4* __restrict__ x) {
    uint32_t i = blockIdx.x * blockDim.x + threadIdx.x;
    if (i >= XWORDS4) return;
    float4 v = x[i];
    union U { __half h[4]; uint2 u; } ph, pl;
    ph.h[0] = __float2half_rn(v.x); ph.h[1] = __float2half_rn(v.y);
    ph.h[2] = __float2half_rn(v.z); ph.h[3] = __float2half_rn(v.w);
    pl.h[0] = __float2half_rn(v.x - __half2float(ph.h[0]));
    pl.h[1] = __float2half_rn(v.y - __half2float(ph.h[1]));
    pl.h[2] = __float2half_rn(v.z - __half2float(ph.h[2]));
    pl.h[3] = __float2half_rn(v.w - __half2float(ph.h[3]));
    ((uint2*)g_xhi)[i] = ph.u;
    ((uint2*)g_xlo)[i] = pl.u;
}

// ---------------------------------------------------------------- barrier
// Only CTAs sharing a batch-block (mb) depend on each other: 16-CTA groups.
__device__ __forceinline__ void group_barrier(int mb) {
    __syncthreads();
    if (threadIdx.x == 0) {
        __threadfence();
        unsigned g0 = ((volatile unsigned*)g_gen)[mb];
        if (atomicAdd(&g_cnt[mb], 1u) == 15u) {
            ((volatile unsigned*)g_cnt)[mb] = 0u;
            __threadfence();
            atomicAdd(&g_gen[mb], 1u);
        } else {
            while (((volatile unsigned*)g_gen)[mb] == g0) { __nanosleep(32); }
        }
        __threadfence();
    }
    __syncthreads();
}

// ---------------------------------------------------------------- main
__global__ void __launch_bounds__(NTHREADS, 1) lstm_persistent(
    const float* __restrict__ W_ih, const float* __restrict__ W_hh,
    const float* __restrict__ b_ih, const float* __restrict__ b_hh,
    const float* __restrict__ hx0, const float* __restrict__ cx0,
    float* __restrict__ out)
{
    extern __shared__ char sm[];
    const uint32_t sb = smem_u32(sm);

    const int tid  = threadIdx.x;
    const int lane = tid & 31;
    const int w    = tid >> 5;
    const int wm   = w >> 1;          // 0..3: rows [wm*32, +32)
    const int wn   = w & 1;           // 0..1: cols [wn*32, +32)
    const int mb   = blockIdx.x >> 4; // batch block (128 rows)
    const int nb   = blockIdx.x & 15; // 16 h-channels

    // ---- build B (hi/lo fp16, [n][k] K-contig, row stride 784B) + bias ----
    // col n: gate g=(n>>3)&3, ch=(n&7)+((n>>5)<<3)  (each 32-col half has all
    // 4 gates for 8 channels -> every thread owns complete i,f,g,o quads)
    for (int idx = tid; idx < 64 * 384; idx += NTHREADS) {
        int n = idx / 384, k = idx - n * 384;
        int g = (n >> 3) & 3, ch = (n & 7) + ((n >> 5) << 3);
        int wr = g * 256 + nb * 16 + ch;
        float v = (k < 128) ? W_ih[wr * 128 + k] : W_hh[wr * 256 + (k - 128)];
        __half hi = __float2half_rn(v);
        __half lo = __float2half_rn(v - __half2float(hi));
        *(__half*)(sm + OFF_BH + n * 784 + k * 2) = hi;
        *(__half*)(sm + OFF_BL + n * 784 + k * 2) = lo;
    }
    if (tid < 64) {
        int g = (tid >> 3) & 3, ch = (tid & 7) + ((tid >> 5) << 3);
        int wr = g * 256 + nb * 16 + ch;
        ((float*)(sm + OFF_BIAS))[tid] = b_ih[wr] + b_hh[wr];
    }

    // ---- init c registers + h0 ping buffer 0 ----
    const int lc2 = 2 * (lane & 3);
    float c_reg[8], h_f[8];
#pragma unroll
    for (int mi = 0; mi < 2; mi++)
#pragma unroll
        for (int rr = 0; rr < 2; rr++)
#pragma unroll
            for (int cc = 0; cc < 2; cc++) {
                int ch = 8 * wn + lc2 + cc;
                c_reg[mi * 4 + rr * 2 + cc] = cx0[nb * 16 + ch];
                h_f[mi * 4 + rr * 2 + cc] = 0.f;
            }
    if (tid < 128) {
        int r = tid;                    // this CTA covers rows mb*128+r
        size_t o = ((size_t)(mb * 128 + r)) * 256 + nb * 16;
#pragma unroll
        for (int ch = 0; ch < 16; ch++) {
            float v = hx0[nb * 16 + ch];
            __half hi = __float2half_rn(v);
            __half lo = __float2half_rn(v - __half2float(hi));
            g_hhi[0][o + ch] = hi;
            g_hlo[0][o + ch] = lo;
        }
    }
    group_barrier(mb);

    // ---- recurrence ----
    for (int t = 0; t < T_STEPS; t++) {
        const int pr = t & 1, pw = pr ^ 1;
        const __half* xh = g_xhi + ((size_t)t * BATCH + mb * 128) * 128;
        const __half* xl = g_xlo + ((size_t)t * BATCH + mb * 128) * 128;
        const __half* hh = g_hhi[pr] + (size_t)(mb * 128) * 256;
        const __half* hl = g_hlo[pr] + (size_t)(mb * 128) * 256;

        float Cacc[2][4][4];
#pragma unroll
        for (int mi = 0; mi < 2; mi++)
#pragma unroll
            for (int ni = 0; ni < 4; ni++)
#pragma unroll
                for (int e = 0; e < 4; e++) Cacc[mi][ni][e] = 0.f;

        for (int ck = 0; ck < 2; ck++) {          // K chunks [0,192),[192,384)
            // fill A chunk (hi/lo), 16B cp.async, 12 iters x 2 per thread
            for (int idx = tid; idx < 128 * 24; idx += NTHREADS) {
                int row = idx / 24, kc = idx - row * 24;
                int gk = ck * 192 + kc * 8;       // global k (halves)
                const __half *sh, *sl;
                if (gk < 128) { sh = xh + row * 128 + gk;
                                sl = xl + row * 128 + gk; }
                else          { sh = hh + row * 256 + (gk - 128);
                                sl = hl + row * 256 + (gk - 128); }
                uint32_t d = sb + OFF_AH + row * 400 + kc * 16;
                cpa16(d, sh);
                cpa16(d + (OFF_AL - OFF_AH), sl);
            }
            CP_COMMIT();
            CP_WAIT0();
            __syncthreads();

            const int kb2 = ck * 384;             // B byte k-offset base
#pragma unroll
            for (int ks = 0; ks < 12; ks++) {
                uint32_t ah[2][4], al[2][4], bh2[2][4], bl2[2][4];
#pragma unroll
                for (int mi = 0; mi < 2; mi++) {
                    uint32_t row = wm * 32 + mi * 16 + (lane & 15);
                    uint32_t a = sb + OFF_AH + row * 400 + ks * 32
                               + ((lane >> 4) << 4);
                    ldsm4(ah[mi], a);
                    ldsm4(al[mi], a + (OFF_AL - OFF_AH));
                }
#pragma unroll
                for (int gn = 0; gn < 2; gn++) {
                    uint32_t n = wn * 32 + gn * 16 + (lane & 7)
                               + ((lane >> 4) << 3);
                    uint32_t ko = ((lane >> 3) & 1) * 16;   // bytes (8 halves)
                    uint32_t a = sb + OFF_BH + n * 784 + kb2 + ks * 32 + ko;
                    ldsm4(bh2[gn], a);
                    ldsm4(bl2[gn], a + (OFF_BL - OFF_BH));
                }
#pragma unroll
                for (int mi = 0; mi < 2; mi++)
#pragma unroll
                    for (int ni = 0; ni < 4; ni++) {
                        const uint32_t* bH = &bh2[ni >> 1][(ni & 1) * 2];
                        const uint32_t* bL = &bl2[ni >> 1][(ni & 1) * 2];
                        mma16816(Cacc[mi][ni], ah[mi], bH);  // Ahi*Bhi
                        mma16816(Cacc[mi][ni], al[mi], bH);  // Alo*Bhi
                        mma16816(Cacc[mi][ni], ah[mi], bL);  // Ahi*Blo
                    }
            }
            __syncthreads();   // all warps done with this A chunk
        }

        // ---- in-register epilogue: gates -> (h,c); h hi/lo to smem ----
        const float* bias = (const float*)(sm + OFF_BIAS);
#pragma unroll
        for (int mi = 0; mi < 2; mi++)
#pragma unroll
            for (int rr = 0; rr < 2; rr++)
#pragma unroll
                for (int cc = 0; cc < 2; cc++) {
                    int ci = rr * 2 + cc;
                    int idx = mi * 4 + ci;
                    int ch = 8 * wn + lc2 + cc;
                    float gi = Cacc[mi][0][ci] + bias[wn * 32 + 0  + lc2 + cc];
                    float gf = Cacc[mi][1][ci] + bias[wn * 32 + 8  + lc2 + cc];
                    float gg = Cacc[mi][2][ci] + bias[wn * 32 + 16 + lc2 + cc];
                    float go = Cacc[mi][3][ci] + bias[wn * 32 + 24 + lc2 + cc];
                    float i_ = sigf(gi), f_ = sigf(gf);
                    float g_ = tanhf_fast(gg), o_ = sigf(go);
                    float cn = f_ * c_reg[idx] + i_ * g_;
                    c_reg[idx] = cn;
                    float hN = o_ * tanhf_fast(cn);
                    h_f[idx] = hN;
                    int r = wm * 32 + mi * 16 + (lane >> 2) + rr * 8;
                    __half hi = __float2half_rn(hN);
                    __half lo = __float2half_rn(hN - __half2float(hi));
                    *(__half*)(sm + OFF_HSH + r * 32 + ch * 2) = hi;
                    *(__half*)(sm + OFF_HSL + r * 32 + ch * 2) = lo;
                }
        __syncthreads();

        // coalesced h -> gmem ping buffer (256 threads, 16B each)
        {
            int r = tid >> 1, part = tid & 1;
            const uint4* s0 = (const uint4*)(sm + OFF_HSH + r * 32 + part * 16);
            const uint4* s1 = (const uint4*)(sm + OFF_HSL + r * 32 + part * 16);
            size_t o = ((size_t)(mb * 128 + r)) * 256 + nb * 16 + part * 8;
            *(uint4*)(g_hhi[pw] + o) = s0[0];
            *(uint4*)(g_hlo[pw] + o) = s1[0];
        }
        group_barrier(mb);
    }

    // ---- output: h (1024x256) then c (1024x256), fp32 ----
#pragma unroll
    for (int mi = 0; mi < 2; mi++)
#pragma unroll
        for (int rr = 0; rr < 2; rr++)
#pragma unroll
            for (int cc = 0; cc < 2; cc++) {
                int idx = mi * 4 + rr * 2 + cc;
                int r = wm * 32 + mi * 16 + (lane >> 2) + rr * 8;
                int ch = 8 * wn + lc2 + cc;
                size_t o = ((size_t)(mb * 128 + r)) * 256 + nb * 16 + ch;
                out[o] = h_f[idx];
                out[(size_t)BATCH * 256 + o] = c_reg[idx];
            }
}

// ---------------------------------------------------------------- launch
extern "C" void kernel_launch(void* const* d_in, const int* in_sizes, int n_in,
                              void* d_out, int out_size) {
    (void)in_sizes; (void)n_in; (void)out_size;
    const float* x    = (const float*)d_in[0];
    const float* W_ih = (const float*)d_in[1];
    const float* W_hh = (const float*)d_in[2];
    const float* b_ih = (const float*)d_in[3];
    const float* b_hh = (const float*)d_in[4];
    const float* hx0  = (const float*)d_in[5];
    const float* cx0  = (const float*)d_in[6];
    float* out = (float*)d_out;

    cudaFuncSetAttribute(lstm_persistent,
                         cudaFuncAttributeMaxDynamicSharedMemorySize, SMEM_DYN);

    lstm_split_x<<<(XWORDS4 + 255) / 256, 256>>>((const float4*)x);
    lstm_persistent<<<NBLK, NTHREADS, SMEM_DYN>>>(W_ih, W_hh, b_ih, b_hh,
                                                  hx0, cx0, out);
}